// round 1
// baseline (speedup 1.0000x reference)
#include <cuda_runtime.h>

#define NCTA 128
#define NTHR 256

constexpr int B = 64, T = 1024, D = 256, H = 256, KXH = 512;

__device__ unsigned g_arrive = 0;
__device__ unsigned g_gen = 0;
__device__ float g_hbase[B * H];

__device__ __forceinline__ void gridbar(unsigned tgt) {
    __syncthreads();
    if (threadIdx.x == 0) {
        __threadfence();
        unsigned a = atomicAdd(&g_arrive, 1u);
        if (a == (unsigned)(NCTA - 1)) {
            g_arrive = 0u;
            __threadfence();
            atomicExch(&g_gen, tgt);
        } else {
            volatile unsigned* p = &g_gen;
            while ((int)(*p - tgt) < 0) { }
        }
        __threadfence();
    }
    __syncthreads();
}

__device__ __forceinline__ float sigmoidf_(float x) {
    return 1.0f / (1.0f + __expf(-x));
}

__device__ __forceinline__ void stage_x(const float* __restrict__ x, float* xh_s, int t) {
    // xh_s[b][0..255] = x[b][t][:]
    for (int f = threadIdx.x; f < B * (D / 4); f += NTHR) {
        int b = f >> 6, q = f & 63;
        float4 v = __ldcg((const float4*)(x + (b * T + t) * D) + q);
        *((float4*)(xh_s + b * KXH) + q) = v;
    }
}

__device__ __forceinline__ void stage_h(const float* __restrict__ h0,
                                        const float* __restrict__ out,
                                        float* xh_s, int t) {
    // xh_s[b][256..511] = h(t) = (t==0 ? h0 : sample(t-1) == out[b][t-1][:])
    for (int f = threadIdx.x; f < B * (H / 4); f += NTHR) {
        int b = f >> 6, q = f & 63;
        float4 v;
        if (t == 0) v = *((const float4*)(h0 + b * H) + q);
        else        v = __ldcg((const float4*)(out + (b * T + (t - 1)) * H) + q);
        *((float4*)(xh_s + b * KXH + D) + q) = v;
    }
}

__device__ __forceinline__ void stage_hb(float* hb_s) {
    for (int f = threadIdx.x; f < B * (H / 4); f += NTHR) {
        int b = f >> 6, q = f & 63;
        float4 v = __ldcg((const float4*)(g_hbase + b * H) + q);
        *((float4*)(hb_s + b * H) + q) = v;
    }
}

__global__ void __launch_bounds__(NTHR, 1) rgru_kernel(
    const float* __restrict__ x, const float* __restrict__ h0,
    const float* __restrict__ eps,
    const float* __restrict__ Wz, const float* __restrict__ bz,
    const float* __restrict__ Wr, const float* __restrict__ br,
    const float* __restrict__ Wtx, const float* __restrict__ btx,
    const float* __restrict__ Wth, const float* __restrict__ bth,
    const float* __restrict__ Wd, const float* __restrict__ bd,
    float* __restrict__ out)
{
    extern __shared__ float smem[];
    float* xh_s = smem;             // [64][512] fp32 = 128KB
    float* hb_s = smem + B * KXH;   // [64][256] fp32 = 64KB

    const int tid = threadIdx.x;
    const int l = tid & 31;         // lane
    const int w = tid >> 5;         // warp 0..7
    const int jj = w & 1;           // which of the CTA's 2 columns
    const int bq = w >> 1;          // batch quarter 0..3
    const int c = blockIdx.x;
    const int j = 2 * c + jj;       // hidden column (0..255), also mean column

    // ---- load all weights this thread ever needs into registers (once) ----
    // lane l owns k-chunks {4l..4l+3, 128+4l.., 256+4l.., 384+4l..} of K=512
    float wz[16], wr[16], wtxr[8], wthr[8], wm[8], wl[8];
#pragma unroll
    for (int q = 0; q < 4; q++)
#pragma unroll
        for (int i = 0; i < 4; i++) {
            int k = q * 128 + 4 * l + i;
            wz[q * 4 + i] = Wz[k * H + j];
            wr[q * 4 + i] = Wr[k * H + j];
        }
#pragma unroll
    for (int i = 0; i < 8; i++) {
        int kx = ((i < 4) ? 0 : 128) + 4 * l + (i & 3);
        wtxr[i] = Wtx[kx * H + j];
        wthr[i] = Wth[kx * H + j];
        wm[i]   = Wd[kx * (2 * H) + j];
        wl[i]   = Wd[kx * (2 * H) + j + H];
    }
    const float bzj = bz[j], brj = br[j], btxj = btx[j], bthj = bth[j];
    const float bdm = bd[j], bdl = bd[j + H];

    // barrier generation base (survives graph replays)
    __shared__ unsigned s_base;
    if (tid == 0) {
        volatile unsigned* p = &g_gen;
        s_base = *p;
    }
    __syncthreads();
    unsigned tgt = s_base;

    stage_x(x, xh_s, 0);
    stage_h(h0, out, xh_s, 0);
    __syncthreads();

    for (int t = 0; t < T; t++) {
        // ================= phase 1: z, r, u, v -> h_base =================
#pragma unroll 2
        for (int bb = 0; bb < 16; bb++) {
            int b = bq * 16 + bb;
            const float4* arow = (const float4*)(xh_s + b * KXH);
            float4 t0 = arow[l];
            float4 t1 = arow[32 + l];
            float4 t2 = arow[64 + l];
            float4 t3 = arow[96 + l];
            float a[16] = { t0.x, t0.y, t0.z, t0.w,  t1.x, t1.y, t1.z, t1.w,
                            t2.x, t2.y, t2.z, t2.w,  t3.x, t3.y, t3.z, t3.w };
            float sz = 0.f, sr = 0.f, su = 0.f, sv = 0.f;
#pragma unroll
            for (int i = 0; i < 16; i++) {
                sz = fmaf(wz[i], a[i], sz);
                sr = fmaf(wr[i], a[i], sr);
            }
#pragma unroll
            for (int i = 0; i < 8; i++) {
                su = fmaf(wtxr[i], a[i], su);       // x part (k<256)
                sv = fmaf(wthr[i], a[8 + i], sv);   // h part (k>=256)
            }
#pragma unroll
            for (int off = 16; off; off >>= 1) {
                sz += __shfl_xor_sync(0xffffffffu, sz, off);
                sr += __shfl_xor_sync(0xffffffffu, sr, off);
                su += __shfl_xor_sync(0xffffffffu, su, off);
                sv += __shfl_xor_sync(0xffffffffu, sv, off);
            }
            if (l == 0) {
                float z = sigmoidf_(sz + bzj);
                float r = sigmoidf_(sr + brj);
                float htil = tanhf(su + btxj + r * (sv + bthj));
                float hp = xh_s[b * KXH + D + j];
                g_hbase[b * H + j] = z * hp + (1.0f - z) * htil;
            }
        }

        tgt++; gridbar(tgt);            // h_base complete grid-wide

        stage_hb(hb_s);
        if (t + 1 < T) stage_x(x, xh_s, t + 1);   // prefetch next x into dead half
        __syncthreads();

        // ================= phase 2: params -> sample =================
#pragma unroll 2
        for (int bb = 0; bb < 16; bb++) {
            int b = bq * 16 + bb;
            const float4* hrow = (const float4*)(hb_s + b * H);
            float4 c0 = hrow[l];
            float4 c1 = hrow[32 + l];
            float hv[8] = { c0.x, c0.y, c0.z, c0.w,  c1.x, c1.y, c1.z, c1.w };
            float sm = 0.f, sl = 0.f;
#pragma unroll
            for (int i = 0; i < 8; i++) {
                sm = fmaf(wm[i], hv[i], sm);
                sl = fmaf(wl[i], hv[i], sl);
            }
#pragma unroll
            for (int off = 16; off; off >>= 1) {
                sm += __shfl_xor_sync(0xffffffffu, sm, off);
                sl += __shfl_xor_sync(0xffffffffu, sl, off);
            }
            if (l == 0) {
                float mean = fminf(fmaxf(sm + bdm, -1000.0f), 1000.0f);
                float lv   = fminf(fmaxf(sl + bdl, -30.0f), 30.0f);
                float e = __ldg(eps + (b * T + t) * H + j);
                out[(b * T + t) * H + j] = fmaf(__expf(0.5f * lv), e, mean);
            }
        }

        tgt++; gridbar(tgt);            // sample(t) complete grid-wide

        if (t + 1 < T) {
            stage_h(h0, out, xh_s, t + 1);
            __syncthreads();
        }
    }

    // second output: h_ts[:, -1, :]
    for (int g = c * NTHR + tid; g < B * H; g += NCTA * NTHR) {
        int b = g >> 8, jx = g & 255;
        out[B * T * H + g] = __ldcg((const float*)(out + (b * T + (T - 1)) * H + jx));
    }
}

extern "C" void kernel_launch(void* const* d_in, const int* in_sizes, int n_in,
                              void* d_out, int out_size) {
    const float* x   = (const float*)d_in[0];
    const float* h0  = (const float*)d_in[1];
    const float* eps = (const float*)d_in[2];
    const float* Wz  = (const float*)d_in[3];
    const float* bz  = (const float*)d_in[4];
    const float* Wr  = (const float*)d_in[5];
    const float* br  = (const float*)d_in[6];
    const float* Wtx = (const float*)d_in[7];
    const float* btx = (const float*)d_in[8];
    const float* Wth = (const float*)d_in[9];
    const float* bth = (const float*)d_in[10];
    const float* Wd  = (const float*)d_in[11];
    const float* bd  = (const float*)d_in[12];
    float* out = (float*)d_out;

    size_t smem = (size_t)(B * KXH + B * H) * sizeof(float);  // 196608
    cudaFuncSetAttribute(rgru_kernel, cudaFuncAttributeMaxDynamicSharedMemorySize, (int)smem);
    rgru_kernel<<<NCTA, NTHR, smem>>>(x, h0, eps, Wz, bz, Wr, br,
                                      Wtx, btx, Wth, bth, Wd, bd, out);
}

// round 2
// speedup vs baseline: 1.5575x; 1.5575x over previous
#include <cuda_runtime.h>

#define NCTA 128
#define NTHR 256

constexpr int B = 64, T = 1024, D = 256, H = 256;
constexpr int GROUPS = 8;          // independent batch groups
constexpr int P = 16;              // CTAs per group (column partition)
constexpr int BG = B / GROUPS;     // 8 batches per group
constexpr int CPC = H / P;         // 16 hidden columns per CTA

__device__ unsigned g_arrive[GROUPS * 32]; // one 128B line per group
__device__ unsigned g_gen[GROUPS * 32];
__device__ float g_hb[B * H];              // h_base exchange [b][j]

__device__ __forceinline__ void groupbar(int g, unsigned tgt) {
    __syncthreads();
    if (threadIdx.x == 0) {
        __threadfence();
        unsigned a = atomicAdd(&g_arrive[g * 32], 1u);
        if (a == (unsigned)(P - 1)) {
            g_arrive[g * 32] = 0u;
            __threadfence();
            atomicExch(&g_gen[g * 32], tgt);
        } else {
            volatile unsigned* q = &g_gen[g * 32];
            while ((int)(*q - tgt) < 0) { }
        }
        __threadfence();
    }
    __syncthreads();
}

__device__ __forceinline__ float sigmoidf_(float x) {
    return 1.0f / (1.0f + __expf(-x));
}

__global__ void __launch_bounds__(NTHR, 1) rgru_kernel(
    const float* __restrict__ x, const float* __restrict__ h0,
    const float* __restrict__ eps,
    const float* __restrict__ Wz, const float* __restrict__ bz,
    const float* __restrict__ Wr, const float* __restrict__ br,
    const float* __restrict__ Wtx, const float* __restrict__ btx,
    const float* __restrict__ Wth, const float* __restrict__ bth,
    const float* __restrict__ Wd, const float* __restrict__ bd,
    float* __restrict__ out)
{
    __shared__ float xh_s[BG][512];     // [b_local][ x(0:256) | h(256:512) ]
    __shared__ float hb_s[BG][256];     // h_base, full row per batch
    __shared__ float eps_s[BG][CPC];    // eps slice for this CTA's columns

    const int tid = threadIdx.x;
    const int l = tid & 31;
    const int w = tid >> 5;            // warp 0..7, owns 2 columns
    const int g = blockIdx.x >> 4;     // group 0..7
    const int p = blockIdx.x & 15;     // partition within group
    const int Jb = p * CPC;            // this CTA's column base
    const int Bb = g * BG;             // this group's batch base
    const int j0 = Jb + 2 * w;         // warp's two global columns: j0, j0+1

    // ---------------- weights into registers (once) ----------------
    // lane l owns k = {128q + 4l + i} ; z/r: q=0..3, u/v/m/lv: q=0..1
    float wz[2][16], wr[2][16], wu[2][8], wv[2][8], wm[2][8], wlv[2][8];
    float bzc[2], brc[2], btxc[2], bthc[2], bmc[2], blc[2];
#pragma unroll
    for (int c = 0; c < 2; c++) {
        int j = j0 + c;
#pragma unroll
        for (int q = 0; q < 4; q++)
#pragma unroll
            for (int i = 0; i < 4; i++) {
                int k = 128 * q + 4 * l + i;
                wz[c][4 * q + i] = Wz[k * H + j];
                wr[c][4 * q + i] = Wr[k * H + j];
            }
#pragma unroll
        for (int q = 0; q < 2; q++)
#pragma unroll
            for (int i = 0; i < 4; i++) {
                int k = 128 * q + 4 * l + i;
                wu[c][4 * q + i]  = Wtx[k * H + j];
                wv[c][4 * q + i]  = Wth[k * H + j];
                wm[c][4 * q + i]  = Wd[k * (2 * H) + j];
                wlv[c][4 * q + i] = Wd[k * (2 * H) + j + H];
            }
        bzc[c] = bz[j]; brc[c] = br[j]; btxc[c] = btx[j]; bthc[c] = bth[j];
        bmc[c] = bd[j]; blc[c] = bd[j + H];
    }

    // barrier generation base (device globals persist across graph replays)
    __shared__ unsigned s_base;
    if (tid == 0) s_base = *(volatile unsigned*)&g_gen[g * 32];
    __syncthreads();
    unsigned tgt = s_base;

    // ---------------- initial staging: x(0), h0 ----------------
    for (int f = tid; f < BG * 64; f += NTHR) {
        int b = f >> 6, q = f & 63;
        ((float4*)xh_s[b])[q] = ((const float4*)(x + ((Bb + b) * T) * D))[q];
    }
    for (int f = tid; f < BG * 64; f += NTHR) {
        int b = f >> 6, q = f & 63;
        ((float4*)(xh_s[b] + 256))[q] = ((const float4*)(h0 + (Bb + b) * H))[q];
    }
    __syncthreads();

    for (int t = 0; t < T; t++) {
        // prefetch eps(t) for this CTA's columns (consumed in phase 2)
        if (tid < 32) {
            int b = l >> 2, q = l & 3;
            ((float4*)eps_s[b])[q] =
                __ldg((const float4*)(eps + ((Bb + b) * T + t) * H + Jb) + q);
        }

        // ================= phase 1: z, r, htil -> h_base =================
#pragma unroll 2
        for (int b = 0; b < BG; b++) {
            const float4* row = (const float4*)xh_s[b];
            float4 t0 = row[l], t1 = row[32 + l], t2 = row[64 + l], t3 = row[96 + l];
            float a[16] = { t0.x, t0.y, t0.z, t0.w,  t1.x, t1.y, t1.z, t1.w,
                            t2.x, t2.y, t2.z, t2.w,  t3.x, t3.y, t3.z, t3.w };
#pragma unroll
            for (int c = 0; c < 2; c++) {
                float sz = 0.f, sr = 0.f, su = 0.f, sv = 0.f;
#pragma unroll
                for (int i = 0; i < 16; i++) {
                    sz = fmaf(wz[c][i], a[i], sz);
                    sr = fmaf(wr[c][i], a[i], sr);
                }
#pragma unroll
                for (int i = 0; i < 8; i++) {
                    su = fmaf(wu[c][i], a[i], su);      // x part (k < 256)
                    sv = fmaf(wv[c][i], a[8 + i], sv);  // h part (k >= 256)
                }
#pragma unroll
                for (int off = 16; off; off >>= 1) {
                    sz += __shfl_xor_sync(0xffffffffu, sz, off);
                    sr += __shfl_xor_sync(0xffffffffu, sr, off);
                    su += __shfl_xor_sync(0xffffffffu, su, off);
                    sv += __shfl_xor_sync(0xffffffffu, sv, off);
                }
                if (l == 0) {
                    int j = j0 + c;
                    float z = sigmoidf_(sz + bzc[c]);
                    float r = sigmoidf_(sr + brc[c]);
                    float htil = tanhf(su + btxc[c] + r * (sv + bthc[c]));
                    float hp = xh_s[b][256 + j];
                    g_hb[(Bb + b) * H + j] = z * hp + (1.0f - z) * htil;
                }
            }
        }

        tgt++; groupbar(g, tgt);   // h_base complete group-wide

        // stage full h_base rows; prefetch x(t+1) into x-half of xh_s
        for (int f = tid; f < BG * 64; f += NTHR) {
            int b = f >> 6, q = f & 63;
            ((float4*)hb_s[b])[q] = __ldcg((const float4*)(g_hb + (Bb + b) * H) + q);
        }
        if (t + 1 < T) {
            for (int f = tid; f < BG * 64; f += NTHR) {
                int b = f >> 6, q = f & 63;
                ((float4*)xh_s[b])[q] =
                    __ldg((const float4*)(x + ((Bb + b) * T + t + 1) * D) + q);
            }
        }
        __syncthreads();

        // ================= phase 2: params -> sample =================
#pragma unroll 2
        for (int b = 0; b < BG; b++) {
            const float4* hrow = (const float4*)hb_s[b];
            float4 c0 = hrow[l], c1 = hrow[32 + l];
            float hv[8] = { c0.x, c0.y, c0.z, c0.w,  c1.x, c1.y, c1.z, c1.w };
#pragma unroll
            for (int c = 0; c < 2; c++) {
                float sm = 0.f, sl = 0.f;
#pragma unroll
                for (int i = 0; i < 8; i++) {
                    sm = fmaf(wm[c][i], hv[i], sm);
                    sl = fmaf(wlv[c][i], hv[i], sl);
                }
#pragma unroll
                for (int off = 16; off; off >>= 1) {
                    sm += __shfl_xor_sync(0xffffffffu, sm, off);
                    sl += __shfl_xor_sync(0xffffffffu, sl, off);
                }
                if (l == 0) {
                    int j = j0 + c;
                    float mean = fminf(fmaxf(sm + bmc[c], -1000.0f), 1000.0f);
                    float lv   = fminf(fmaxf(sl + blc[c], -30.0f), 30.0f);
                    float s = fmaf(__expf(0.5f * lv), eps_s[b][2 * w + c], mean);
                    out[((Bb + b) * T + t) * H + j] = s;
                    if (t == T - 1) out[B * T * H + (Bb + b) * H + j] = s;
                }
            }
        }

        tgt++; groupbar(g, tgt);   // sample(t) complete group-wide

        // stage h(t+1) = sample(t) into h-half of xh_s
        if (t + 1 < T) {
            for (int f = tid; f < BG * 64; f += NTHR) {
                int b = f >> 6, q = f & 63;
                ((float4*)(xh_s[b] + 256))[q] =
                    __ldcg((const float4*)(out + ((Bb + b) * T + t) * H) + q);
            }
            __syncthreads();
        }
    }
}

extern "C" void kernel_launch(void* const* d_in, const int* in_sizes, int n_in,
                              void* d_out, int out_size) {
    const float* x   = (const float*)d_in[0];
    const float* h0  = (const float*)d_in[1];
    const float* eps = (const float*)d_in[2];
    const float* Wz  = (const float*)d_in[3];
    const float* bz  = (const float*)d_in[4];
    const float* Wr  = (const float*)d_in[5];
    const float* br  = (const float*)d_in[6];
    const float* Wtx = (const float*)d_in[7];
    const float* btx = (const float*)d_in[8];
    const float* Wth = (const float*)d_in[9];
    const float* bth = (const float*)d_in[10];
    const float* Wd  = (const float*)d_in[11];
    const float* bd  = (const float*)d_in[12];
    float* out = (float*)d_out;

    rgru_kernel<<<NCTA, NTHR>>>(x, h0, eps, Wz, bz, Wr, br,
                                Wtx, btx, Wth, bth, Wd, bd, out);
}